// round 15
// baseline (speedup 1.0000x reference)
#include <cuda_runtime.h>
#include <cuda_fp16.h>
#include <stdint.h>

#define BB 256
#define TT 128
#define II 256
#define HH 1024
#define CC 1000

typedef __half hf;

// ---------------- device scratch (allocation-free) ----------------
__device__ float g_xp0[(size_t)BB * TT * HH];
__device__ float g_xp1[(size_t)BB * TT * HH];
__device__ hf g_xh[(size_t)BB * TT * II];
__device__ hf g_h2f[(size_t)BB * HH];              // final h2[:,T-1,:] fp16 for FC
__device__ int8_t g_h1q1[(size_t)BB * TT * HH];
__device__ int8_t g_h1q2[(size_t)BB * TT * HH];
__device__ int8_t g_h2q1[(size_t)BB * TT * HH];
__device__ int8_t g_h2q2[(size_t)BB * TT * HH];
__device__ hf g_Wih0hi[HH * II];  __device__ hf g_Wih0lo[HH * II];
__device__ int8_t g_Whh0a[HH * HH];  __device__ int8_t g_Whh0b[HH * HH];
__device__ int8_t g_Wih1a[HH * HH];  __device__ int8_t g_Wih1b[HH * HH];
__device__ int8_t g_Whh1a[HH * HH];  __device__ int8_t g_Whh1b[HH * HH];
__device__ hf g_fcWhi[HH * HH];   __device__ hf g_fcWlo[HH * HH];

// ---------------- helpers ----------------
__device__ __forceinline__ uint32_t smem_u32(const void* p) {
    uint32_t a;
    asm("{ .reg .u64 t; cvta.to.shared.u64 t, %1; cvt.u32.u64 %0, t; }" : "=r"(a) : "l"(p));
    return a;
}
__device__ __forceinline__ void cp16(uint32_t dst, const void* src) {
    asm volatile("cp.async.cg.shared.global [%0], [%1], 16;" :: "r"(dst), "l"(src) : "memory");
}
#define CP_COMMIT() asm volatile("cp.async.commit_group;" ::: "memory")
#define CP_WAITG(n) asm volatile("cp.async.wait_group %0;" :: "n"(n) : "memory")

__device__ __forceinline__ void ldsm4(uint32_t* r, uint32_t addr) {
    asm volatile("ldmatrix.sync.aligned.m8n8.x4.shared.b16 {%0,%1,%2,%3}, [%4];"
        : "=r"(r[0]), "=r"(r[1]), "=r"(r[2]), "=r"(r[3]) : "r"(addr));
}
__device__ __forceinline__ void mma16816(float* c, const uint32_t* a, const uint32_t* b) {
    asm volatile(
        "mma.sync.aligned.m16n8k16.row.col.f32.f16.f16.f32 "
        "{%0,%1,%2,%3}, {%4,%5,%6,%7}, {%8,%9}, {%0,%1,%2,%3};"
        : "+f"(c[0]), "+f"(c[1]), "+f"(c[2]), "+f"(c[3])
        : "r"(a[0]), "r"(a[1]), "r"(a[2]), "r"(a[3]), "r"(b[0]), "r"(b[1]));
}
__device__ __forceinline__ void imma16832(int* c, const uint32_t* a, const uint32_t* b) {
    asm volatile(
        "mma.sync.aligned.m16n8k32.row.col.s32.s8.s8.s32 "
        "{%0,%1,%2,%3}, {%4,%5,%6,%7}, {%8,%9}, {%0,%1,%2,%3};"
        : "+r"(c[0]), "+r"(c[1]), "+r"(c[2]), "+r"(c[3])
        : "r"(a[0]), "r"(a[1]), "r"(a[2]), "r"(a[3]), "r"(b[0]), "r"(b[1]));
}
__device__ __forceinline__ float fast_tanh(float x) {
    float e = __expf(2.f * x);
    return 1.f - __fdividef(2.f, e + 1.f);
}

#define PAD_STRIDE 72
#define ROWB 144

// ---------------- prep kernels ----------------
__global__ void splitw_kernel(const float* __restrict__ s, hf* __restrict__ hi,
                              hf* __restrict__ lo, int n) {
    int i = blockIdx.x * blockDim.x + threadIdx.x;
    if (i >= n) return;
    float v = s[i];
    hf h = __float2half(v);
    hi[i] = h;
    lo[i] = __float2half(v - __half2float(h));
}
__global__ void cvt_kernel(const float* __restrict__ s, hf* __restrict__ d, int n) {
    int i = blockIdx.x * blockDim.x + threadIdx.x;
    if (i < n) d[i] = __float2half(s[i]);
}
__global__ void split_pad_fc(const float* __restrict__ s, hf* __restrict__ hi,
                             hf* __restrict__ lo) {
    int i = blockIdx.x * blockDim.x + threadIdx.x;
    if (i >= HH * HH) return;
    int r = i >> 10, c = i & 1023;
    float v = (r < CC) ? s[r * HH + c] : 0.f;
    hf h = __float2half(v);
    hi[i] = h;
    lo[i] = __float2half(v - __half2float(h));
}
// W -> int8 pair: W ~ a*2^-12 + b*2^-18
__global__ void quantw_kernel(const float* __restrict__ s, int8_t* __restrict__ wa,
                              int8_t* __restrict__ wb, int n) {
    int i = blockIdx.x * blockDim.x + threadIdx.x;
    if (i >= n) return;
    float v = s[i];
    int a = __float2int_rn(v * 4096.f);
    a = max(-127, min(127, a));
    float r = v - (float)a * 0x1p-12f;
    int b = __float2int_rn(r * 262144.f);
    b = max(-127, min(127, b));
    wa[i] = (int8_t)a;
    wb[i] = (int8_t)b;
}

// ---------------- fp16 2-term GEMM (bulk proj EPI 0 / FC EPI 2) — proven R12 path ----------------
struct MLArgs {
    const hf *A, *Whi, *Wlo;
    size_t rowA0, strideA;
    int K;
};

__device__ __forceinline__ void run_ml_fp16(
    float acc[4][4], const MLArgs& ml, hf* sA, hf* sB, int tid, int bm, int bn)
{
    const int lane = tid & 31, wid = tid >> 5;
    const int wm = wid & 1, wn = wid >> 1;
    const uint32_t sAu = smem_u32(sA);
    const uint32_t sBu = smem_u32(sB);
    const int CPT = ml.K / 64, NC = 2 * CPT;

    auto load_chunk = [&](int c, int s) {
        int term = c / CPT;
        int kk = (c - term * CPT) * 64;
        const hf* Wg = term ? ml.Wlo : ml.Whi;
        uint32_t Ab = sAu + s * (32 * ROWB);
        uint32_t Bb = sBu + s * (64 * ROWB);
        #pragma unroll
        for (int i = 0; i < 2; i++) {
            int task = tid + i * 128;
            int row = task >> 3, seg = task & 7;
            cp16(Ab + row * ROWB + seg * 16,
                 ml.A + ml.rowA0 + (size_t)(bm * 32 + row) * ml.strideA + kk + seg * 8);
        }
        #pragma unroll
        for (int i = 0; i < 4; i++) {
            int task = tid + i * 128;
            int row = task >> 3, seg = task & 7;
            cp16(Bb + row * ROWB + seg * 16,
                 Wg + (size_t)(bn * 64 + row) * ml.K + kk + seg * 8);
        }
        CP_COMMIT();
    };

    const uint32_t aOff = (uint32_t)(wm * 16 + (lane & 15)) * ROWB + ((lane >> 4) & 1) * 16;
    const uint32_t bOff = (uint32_t)(wn * 32 + ((lane >> 4) & 1) * 8 + (lane & 7)) * ROWB
                          + ((lane >> 3) & 1) * 16;

    load_chunk(0, 0);
    load_chunk(1, 1);
    for (int c = 0; c < NC; c++) {
        int s = c - (c / 3) * 3;
        if (c + 1 < NC) { CP_WAITG(1); }
        else            { CP_WAITG(0); }
        __syncthreads();
        uint32_t Ab = sAu + s * (32 * ROWB) + aOff;
        uint32_t Bb = sBu + s * (64 * ROWB) + bOff;
        #pragma unroll
        for (int k16 = 0; k16 < 4; k16++) {
            uint32_t a[4], b01[4], b23[4];
            ldsm4(a, Ab + k16 * 32);
            ldsm4(b01, Bb + k16 * 32);
            ldsm4(b23, Bb + 16 * ROWB + k16 * 32);
            mma16816(acc[0], a, b01);
            mma16816(acc[1], a, b01 + 2);
            mma16816(acc[2], a, b23);
            mma16816(acc[3], a, b23 + 2);
        }
        __syncthreads();
        if (c + 2 < NC) load_chunk(c + 2, (c + 2) - ((c + 2) / 3) * 3);
    }
}

template <int EPI>
__global__ void __launch_bounds__(128) gemm_kernel(
    const hf* __restrict__ A, size_t rowA0, size_t strideA, int K,
    const hf* __restrict__ Whi, const hf* __restrict__ Wlo,
    const float* __restrict__ e0, const float* __restrict__ e1,
    float* __restrict__ outF, size_t rowO0, size_t strideO)
{
    __shared__ __align__(16) hf sA[3][32 * PAD_STRIDE];
    __shared__ __align__(16) hf sB[3][64 * PAD_STRIDE];

    const int tid = threadIdx.x;
    const int bn = blockIdx.x, bm = blockIdx.y;
    const int wid = tid >> 5, lane = tid & 31;
    const int g = lane >> 2, tg = lane & 3;
    const int wm = wid & 1, wn = wid >> 1;

    float acc[4][4];
    #pragma unroll
    for (int i = 0; i < 4; i++)
        #pragma unroll
        for (int j = 0; j < 4; j++) acc[i][j] = 0.f;

    MLArgs ml{A, Whi, Wlo, rowA0, strideA, K};
    run_ml_fp16(acc, ml, &sA[0][0], &sB[0][0], tid, bm, bn);

    const int r0 = bm * 32 + wm * 16 + g;
    #pragma unroll
    for (int nt = 0; nt < 4; nt++) {
        int n = bn * 64 + wn * 32 + nt * 8 + tg * 2;
        if (EPI == 2 && n >= CC) continue;
        float b0 = (EPI == 0) ? (e0[n] + e1[n]) : e0[n];
        float b1 = (EPI == 0) ? (e0[n + 1] + e1[n + 1]) : e0[n + 1];
        float* p0 = outF + rowO0 + (size_t)r0 * strideO + n;
        float* p1 = outF + rowO0 + (size_t)(r0 + 8) * strideO + n;
        ((float2*)p0)[0] = make_float2(acc[nt][0] + b0, acc[nt][1] + b1);
        ((float2*)p1)[0] = make_float2(acc[nt][2] + b0, acc[nt][3] + b1);
    }
}

// ---------------- int8 3-term round kernel ----------------
// Phase z = blockIdx.z, t = r - z:
//  z=0: h1[t] = tanh(xp0[t] + Whh0 @ h1[t-1])
//  z=1: xp1[t] = Wih1 @ h1[t] + bih1 + bhh1
//  z=2: h2[t] = tanh(xp1[t] + Whh1 @ h2[t-1])
// A = q1·2^-7 + q2·2^-13 (int8), W = wa·2^-12 + wb·2^-18 (int8).
// terms: 0:(q1,wa) scale 2^-19 | 1:(q1,wb) scale 2^-25 | 2:(q2,wa) scale 2^-25.
// Chunk = 128 int8 along K (128B rows, identical byte layout to fp16 chunks).
__global__ void __launch_bounds__(128) round_kernel(
    int r, const float* __restrict__ bih1, const float* __restrict__ bhh1)
{
    const int z = blockIdx.z;
    const int t = r - z;
    if (t < 0 || t >= TT) return;

    const size_t TH = (size_t)TT * HH;
    const int8_t *Aq1, *Aq2, *Wa, *Wb;
    size_t rowA0 = 0;
    bool doGemm = true;
    if (z == 0) {
        Aq1 = g_h1q1; Aq2 = g_h1q2; Wa = g_Whh0a; Wb = g_Whh0b;
        rowA0 = (size_t)(t - 1) * HH;  doGemm = (t > 0);
    } else if (z == 1) {
        Aq1 = g_h1q1; Aq2 = g_h1q2; Wa = g_Wih1a; Wb = g_Wih1b;
        rowA0 = (size_t)t * HH;
    } else {
        Aq1 = g_h2q1; Aq2 = g_h2q2; Wa = g_Whh1a; Wb = g_Whh1b;
        rowA0 = (size_t)(t - 1) * HH;  doGemm = (t > 0);
    }

    __shared__ __align__(16) int8_t sA[3][32 * ROWB];
    __shared__ __align__(16) int8_t sB[3][64 * ROWB];

    const int tid = threadIdx.x;
    const int bn = blockIdx.x, bm = blockIdx.y;
    const int wid = tid >> 5, lane = tid & 31;
    const int g = lane >> 2, tg = lane & 3;
    const int wm = wid & 1, wn = wid >> 1;

    float facc[4][4];
    #pragma unroll
    for (int i = 0; i < 4; i++)
        #pragma unroll
        for (int j = 0; j < 4; j++) facc[i][j] = 0.f;

    if (doGemm) {
        const uint32_t sAu = smem_u32(sA);
        const uint32_t sBu = smem_u32(sB);
        const int NC = 24;                     // 3 terms x 8 chunks

        auto load_chunk = [&](int c, int s) {
            int term = c >> 3;
            int kk = (c & 7) * 128;
            const int8_t* Ag = (term < 2) ? Aq1 : Aq2;
            const int8_t* Wg = (term == 1) ? Wb : Wa;
            uint32_t Ab = sAu + s * (32 * ROWB);
            uint32_t Bb = sBu + s * (64 * ROWB);
            #pragma unroll
            for (int i = 0; i < 2; i++) {      // A: 32 rows x 8 segs of 16B
                int task = tid + i * 128;
                int row = task >> 3, seg = task & 7;
                cp16(Ab + row * ROWB + seg * 16,
                     Ag + rowA0 + (size_t)(bm * 32 + row) * TH + kk + seg * 16);
            }
            #pragma unroll
            for (int i = 0; i < 4; i++) {      // B: 64 rows x 8 segs of 16B
                int task = tid + i * 128;
                int row = task >> 3, seg = task & 7;
                cp16(Bb + row * ROWB + seg * 16,
                     Wg + (size_t)(bn * 64 + row) * HH + kk + seg * 16);
            }
            CP_COMMIT();
        };

        const uint32_t aOff = (uint32_t)(wm * 16 + (lane & 15)) * ROWB + ((lane >> 4) & 1) * 16;
        const uint32_t bOff = (uint32_t)(wn * 32 + ((lane >> 4) & 1) * 8 + (lane & 7)) * ROWB
                              + ((lane >> 3) & 1) * 16;

        int iacc[4][4];
        #pragma unroll
        for (int i = 0; i < 4; i++)
            #pragma unroll
            for (int j = 0; j < 4; j++) iacc[i][j] = 0;

        const float SCL[3] = {0x1p-19f, 0x1p-25f, 0x1p-25f};

        load_chunk(0, 0);
        load_chunk(1, 1);
        for (int c = 0; c < NC; c++) {
            int s = c - (c / 3) * 3;
            if (c + 1 < NC) { CP_WAITG(1); }
            else            { CP_WAITG(0); }
            __syncthreads();
            uint32_t Ab = sAu + s * (32 * ROWB) + aOff;
            uint32_t Bb = sBu + s * (64 * ROWB) + bOff;
            #pragma unroll
            for (int ks = 0; ks < 4; ks++) {   // 4 k32 steps of 32B
                uint32_t a[4], b01[4], b23[4];
                ldsm4(a, Ab + ks * 32);
                ldsm4(b01, Bb + ks * 32);
                ldsm4(b23, Bb + 16 * ROWB + ks * 32);
                imma16832(iacc[0], a, b01);
                imma16832(iacc[1], a, b01 + 2);
                imma16832(iacc[2], a, b23);
                imma16832(iacc[3], a, b23 + 2);
            }
            __syncthreads();
            if (c + 2 < NC) load_chunk(c + 2, (c + 2) - ((c + 2) / 3) * 3);
            if ((c & 7) == 7) {                // term boundary: drain int acc
                float scl = SCL[c >> 3];
                #pragma unroll
                for (int i = 0; i < 4; i++)
                    #pragma unroll
                    for (int j = 0; j < 4; j++) {
                        facc[i][j] += (float)iacc[i][j] * scl;
                        iacc[i][j] = 0;
                    }
            }
        }
    }

    // ---------------- epilogue ----------------
    const int r0 = bm * 32 + wm * 16 + g;
    const size_t rowT = (size_t)t * HH;

    #pragma unroll
    for (int nt = 0; nt < 4; nt++) {
        int n = bn * 64 + wn * 32 + nt * 8 + tg * 2;
        if (z == 1) {
            float b0 = bih1[n] + bhh1[n], b1 = bih1[n + 1] + bhh1[n + 1];
            float* p0 = g_xp1 + rowT + (size_t)r0 * TH + n;
            float* p1 = g_xp1 + rowT + (size_t)(r0 + 8) * TH + n;
            ((float2*)p0)[0] = make_float2(facc[nt][0] + b0, facc[nt][1] + b1);
            ((float2*)p1)[0] = make_float2(facc[nt][2] + b0, facc[nt][3] + b1);
        } else {
            const float* xps = (z == 0) ? g_xp0 : g_xp1;
            int8_t* oq1 = (z == 0) ? g_h1q1 : g_h2q1;
            int8_t* oq2 = (z == 0) ? g_h1q2 : g_h2q2;
            #pragma unroll
            for (int h = 0; h < 2; h++) {
                int rr = r0 + h * 8;
                const float2 xp2 = *(const float2*)(xps + rowT + (size_t)rr * TH + n);
                float v0 = fast_tanh(facc[nt][h * 2 + 0] + xp2.x);
                float v1 = fast_tanh(facc[nt][h * 2 + 1] + xp2.y);
                // quantize: v ~ q1*2^-7 + q2*2^-13
                int a0 = max(-127, min(127, __float2int_rn(v0 * 128.f)));
                int a1 = max(-127, min(127, __float2int_rn(v1 * 128.f)));
                int c0 = __float2int_rn((v0 - (float)a0 * 0x1p-7f) * 8192.f);
                int c1 = __float2int_rn((v1 - (float)a1 * 0x1p-7f) * 8192.f);
                size_t go = rowT + (size_t)rr * TH + n;
                char2 p1c; p1c.x = (char)a0; p1c.y = (char)a1;
                char2 p2c; p2c.x = (char)c0; p2c.y = (char)c1;
                *(char2*)(oq1 + go) = p1c;
                *(char2*)(oq2 + go) = p2c;
                if (z == 2 && t == TT - 1) {
                    __half2 hp;
                    hp.x = __float2half(v0);
                    hp.y = __float2half(v1);
                    *(__half2*)(g_h2f + (size_t)rr * HH + n) = hp;
                }
            }
        }
    }
}

// ---------------- host ----------------
extern "C" void kernel_launch(void* const* d_in, const int* in_sizes, int n_in,
                              void* d_out, int out_size)
{
    const float* x    = (const float*)d_in[0];
    const float* Wih0 = (const float*)d_in[1];
    const float* Whh0 = (const float*)d_in[2];
    const float* bih0 = (const float*)d_in[3];
    const float* bhh0 = (const float*)d_in[4];
    const float* Wih1 = (const float*)d_in[5];
    const float* Whh1 = (const float*)d_in[6];
    const float* bih1 = (const float*)d_in[7];
    const float* bhh1 = (const float*)d_in[8];
    const float* fcW  = (const float*)d_in[9];
    const float* fcb  = (const float*)d_in[10];
    float* out = (float*)d_out;

    void *p_xp0, *p_xh, *p_h2f, *p_i0h, *p_i0l, *p_fch, *p_fcl;
    void *p_r0a, *p_r0b, *p_i1a, *p_i1b, *p_r1a, *p_r1b;
    cudaGetSymbolAddress(&p_xp0, g_xp0);
    cudaGetSymbolAddress(&p_xh, g_xh);
    cudaGetSymbolAddress(&p_h2f, g_h2f);
    cudaGetSymbolAddress(&p_i0h, g_Wih0hi); cudaGetSymbolAddress(&p_i0l, g_Wih0lo);
    cudaGetSymbolAddress(&p_fch, g_fcWhi);  cudaGetSymbolAddress(&p_fcl, g_fcWlo);
    cudaGetSymbolAddress(&p_r0a, g_Whh0a);  cudaGetSymbolAddress(&p_r0b, g_Whh0b);
    cudaGetSymbolAddress(&p_i1a, g_Wih1a);  cudaGetSymbolAddress(&p_i1b, g_Wih1b);
    cudaGetSymbolAddress(&p_r1a, g_Whh1a);  cudaGetSymbolAddress(&p_r1b, g_Whh1b);

    // 1. conversions / splits / quants
    cvt_kernel<<<(BB * TT * II + 255) / 256, 256>>>(x, (hf*)p_xh, BB * TT * II);
    splitw_kernel<<<(HH * II + 255) / 256, 256>>>(Wih0, (hf*)p_i0h, (hf*)p_i0l, HH * II);
    quantw_kernel<<<(HH * HH + 255) / 256, 256>>>(Whh0, (int8_t*)p_r0a, (int8_t*)p_r0b, HH * HH);
    quantw_kernel<<<(HH * HH + 255) / 256, 256>>>(Wih1, (int8_t*)p_i1a, (int8_t*)p_i1b, HH * HH);
    quantw_kernel<<<(HH * HH + 255) / 256, 256>>>(Whh1, (int8_t*)p_r1a, (int8_t*)p_r1b, HH * HH);
    split_pad_fc<<<(HH * HH + 255) / 256, 256>>>(fcW, (hf*)p_fch, (hf*)p_fcl);

    const dim3 projGrid(HH / 64, (BB * TT) / 32);   // (16, 1024)
    const dim3 roundGrid(HH / 64, BB / 32, 3);      // (16, 8, 3)
    const dim3 fcGrid(HH / 64, BB / 32);            // (16, 8)

    // 2. layer0 bulk input projection: xp0 = x @ Wih0^T + bih0 + bhh0  (fp16 2-term)
    gemm_kernel<0><<<projGrid, 128>>>(
        (hf*)p_xh, 0, II, II,
        (hf*)p_i0h, (hf*)p_i0l, bih0, bhh0,
        (float*)p_xp0, 0, HH);

    // 3. pipelined rounds (int8 3-term IMMA)
    for (int r = 0; r <= TT + 1; r++)
        round_kernel<<<roundGrid, 128>>>(r, bih1, bhh1);

    // 4. FC on h2f  (fp16 2-term)
    gemm_kernel<2><<<fcGrid, 128>>>(
        (hf*)p_h2f, 0, HH, HH,
        (hf*)p_fch, (hf*)p_fcl, fcb, nullptr,
        out, 0, CC);
}

// round 17
// speedup vs baseline: 3.2565x; 3.2565x over previous
#include <cuda_runtime.h>
#include <cuda_fp16.h>
#include <stdint.h>

#define BB 256
#define TT 128
#define II 256
#define HH 1024
#define CC 1000

typedef __half hf;

// ---------------- device scratch (allocation-free) ----------------
__device__ float g_xp0[(size_t)BB * TT * HH];
__device__ float g_xp1[(size_t)BB * TT * HH];
__device__ hf g_xh[(size_t)BB * TT * II];
__device__ hf g_h1[(size_t)BB * TT * HH];
__device__ hf g_h2[(size_t)BB * TT * HH];
__device__ hf g_Wih0hi[HH * II];  __device__ hf g_Wih0lo[HH * II];
__device__ hf g_Whh0hi[HH * HH];  __device__ hf g_Whh0lo[HH * HH];
__device__ hf g_Wih1hi[HH * HH];  __device__ hf g_Wih1lo[HH * HH];
__device__ hf g_Whh1hi[HH * HH];  __device__ hf g_Whh1lo[HH * HH];
__device__ hf g_fcWhi[HH * HH];   __device__ hf g_fcWlo[HH * HH];

// ---------------- helpers ----------------
__device__ __forceinline__ uint32_t smem_u32(const void* p) {
    uint32_t a;
    asm("{ .reg .u64 t; cvta.to.shared.u64 t, %1; cvt.u32.u64 %0, t; }" : "=r"(a) : "l"(p));
    return a;
}
__device__ __forceinline__ void cp16(uint32_t dst, const void* src) {
    asm volatile("cp.async.cg.shared.global [%0], [%1], 16;" :: "r"(dst), "l"(src) : "memory");
}
#define CP_COMMIT() asm volatile("cp.async.commit_group;" ::: "memory")
#define CP_WAITG(n) asm volatile("cp.async.wait_group %0;" :: "n"(n) : "memory")

__device__ __forceinline__ void ldsm4(uint32_t* r, uint32_t addr) {
    asm volatile("ldmatrix.sync.aligned.m8n8.x4.shared.b16 {%0,%1,%2,%3}, [%4];"
        : "=r"(r[0]), "=r"(r[1]), "=r"(r[2]), "=r"(r[3]) : "r"(addr));
}
__device__ __forceinline__ void mma16816(float* c, const uint32_t* a, const uint32_t* b) {
    asm volatile(
        "mma.sync.aligned.m16n8k16.row.col.f32.f16.f16.f32 "
        "{%0,%1,%2,%3}, {%4,%5,%6,%7}, {%8,%9}, {%0,%1,%2,%3};"
        : "+f"(c[0]), "+f"(c[1]), "+f"(c[2]), "+f"(c[3])
        : "r"(a[0]), "r"(a[1]), "r"(a[2]), "r"(a[3]), "r"(b[0]), "r"(b[1]));
}
__device__ __forceinline__ float fast_tanh(float x) {
    float e = __expf(2.f * x);
    return 1.f - __fdividef(2.f, e + 1.f);
}

// smem layout (dynamic): 3 stages of [A 32x72hf | Bhi 64x72hf | Blo 64x72hf]
#define ROWB 144
#define ASTG 4608            // 32*144
#define BSTG 9216            // 64*144
#define STG  23040           // ASTG + 2*BSTG
#define SMEM_DYN (3 * STG)   // 69120

// ---------------- split kernels ----------------
__global__ void splitw_kernel(const float* __restrict__ s, hf* __restrict__ hi,
                              hf* __restrict__ lo, int n) {
    int i = blockIdx.x * blockDim.x + threadIdx.x;
    if (i >= n) return;
    float v = s[i];
    hf h = __float2half(v);
    hi[i] = h;
    lo[i] = __float2half(v - __half2float(h));
}
__global__ void cvt_kernel(const float* __restrict__ s, hf* __restrict__ d, int n) {
    int i = blockIdx.x * blockDim.x + threadIdx.x;
    if (i < n) d[i] = __float2half(s[i]);
}
__global__ void split_pad_fc(const float* __restrict__ s, hf* __restrict__ hi,
                             hf* __restrict__ lo) {
    int i = blockIdx.x * blockDim.x + threadIdx.x;
    if (i >= HH * HH) return;
    int r = i >> 10, c = i & 1023;
    float v = (r < CC) ? s[r * HH + c] : 0.f;
    hf h = __float2half(v);
    hi[i] = h;
    lo[i] = __float2half(v - __half2float(h));
}

// ---------------- fused-term mainloop ----------------
// 256 threads. warp-group wg (wid>>2): 0 -> A@Whi, 1 -> A@Wlo.
// single=true: only hi term (wg1 skips compute but keeps syncs; Blo not loaded).
__device__ __forceinline__ void run_ml(
    float acc[4][4],
    const hf* __restrict__ A, const hf* __restrict__ Whi, const hf* __restrict__ Wlo,
    size_t rowA0, size_t strideA, int K,
    uint32_t sm, int tid, int bm, int bn, int wg, int wq, bool single)
{
    const int lane = tid & 31;
    const int wm = wq & 1, wn = wq >> 1;
    const int NC = K / 64;

    auto load_chunk = [&](int c, int s) {
        int kk = c * 64;
        uint32_t st = sm + s * STG;
        {   // A: 32 rows x 8 segs = 256 tasks, 1/thread
            int row = tid >> 3, seg = tid & 7;
            cp16(st + row * ROWB + seg * 16,
                 A + rowA0 + (size_t)(bm * 32 + row) * strideA + kk + seg * 8);
        }
        #pragma unroll
        for (int i = 0; i < 2; i++) {   // Bhi (+ Blo when 2-term): 64 rows x 8 segs
            int task = tid + i * 256;
            int row = task >> 3, seg = task & 7;
            size_t go = (size_t)(bn * 64 + row) * K + kk + seg * 8;
            cp16(st + ASTG + row * ROWB + seg * 16, Whi + go);
            if (!single)
                cp16(st + ASTG + BSTG + row * ROWB + seg * 16, Wlo + go);
        }
        CP_COMMIT();
    };

    const uint32_t aOff = (uint32_t)(wm * 16 + (lane & 15)) * ROWB + ((lane >> 4) & 1) * 16;
    const uint32_t bOff = (uint32_t)(wn * 32 + ((lane >> 4) & 1) * 8 + (lane & 7)) * ROWB
                          + ((lane >> 3) & 1) * 16;
    const uint32_t bBase = ASTG + (uint32_t)wg * BSTG;
    const bool active = !(single && wg == 1);

    load_chunk(0, 0);
    load_chunk(1, 1);
    for (int c = 0; c < NC; c++) {
        int s = c - (c / 3) * 3;
        if (c + 1 < NC) { CP_WAITG(1); }
        else            { CP_WAITG(0); }
        __syncthreads();
        if (active) {
            uint32_t Ab = sm + s * STG + aOff;
            uint32_t Bb = sm + s * STG + bBase + bOff;
            #pragma unroll
            for (int k16 = 0; k16 < 4; k16++) {
                uint32_t a[4], b01[4], b23[4];
                ldsm4(a, Ab + k16 * 32);
                ldsm4(b01, Bb + k16 * 32);
                ldsm4(b23, Bb + 16 * ROWB + k16 * 32);
                mma16816(acc[0], a, b01);
                mma16816(acc[1], a, b01 + 2);
                mma16816(acc[2], a, b23);
                mma16816(acc[3], a, b23 + 2);
            }
        }
        __syncthreads();
        if (c + 2 < NC) load_chunk(c + 2, (c + 2) - ((c + 2) / 3) * 3);
    }
}

// ---------------- generic GEMM (bulk proj EPI 0, FC EPI 2) ----------------
template <int EPI>
__global__ void __launch_bounds__(256) gemm_kernel(
    const hf* __restrict__ A, size_t rowA0, size_t strideA, int K,
    const hf* __restrict__ Whi, const hf* __restrict__ Wlo,
    const float* __restrict__ e0, const float* __restrict__ e1,
    float* __restrict__ outF, size_t rowO0, size_t strideO)
{
    extern __shared__ __align__(16) char smem_raw[];
    uint32_t sm = smem_u32(smem_raw);
    const int tid = threadIdx.x;
    const int bn = blockIdx.x, bm = blockIdx.y;
    const int lane = tid & 31, wid = tid >> 5;
    const int wg = wid >> 2, wq = wid & 3;
    const int wm = wq & 1, wn = wq >> 1;
    const int g = lane >> 2, tg = lane & 3;

    float acc[4][4];
    #pragma unroll
    for (int i = 0; i < 4; i++)
        #pragma unroll
        for (int j = 0; j < 4; j++) acc[i][j] = 0.f;

    run_ml(acc, A, Whi, Wlo, rowA0, strideA, K, sm, tid, bm, bn, wg, wq, false);

    // cross-group reduction: lo group -> smem, hi group adds
    float* red = (float*)smem_raw;
    if (wg == 1) {
        #pragma unroll
        for (int nt = 0; nt < 4; nt++)
            #pragma unroll
            for (int j = 0; j < 4; j++) red[(tid - 128) * 16 + nt * 4 + j] = acc[nt][j];
    }
    __syncthreads();
    if (wg == 0) {
        #pragma unroll
        for (int nt = 0; nt < 4; nt++)
            #pragma unroll
            for (int j = 0; j < 4; j++) acc[nt][j] += red[tid * 16 + nt * 4 + j];

        const int r0 = bm * 32 + wm * 16 + g;
        #pragma unroll
        for (int nt = 0; nt < 4; nt++) {
            int n = bn * 64 + wn * 32 + nt * 8 + tg * 2;
            if (EPI == 2 && n >= CC) continue;
            float b0 = (EPI == 0) ? (e0[n] + e1[n]) : e0[n];
            float b1 = (EPI == 0) ? (e0[n + 1] + e1[n + 1]) : e0[n + 1];
            float* p0 = outF + rowO0 + (size_t)r0 * strideO + n;
            float* p1 = outF + rowO0 + (size_t)(r0 + 8) * strideO + n;
            ((float2*)p0)[0] = make_float2(acc[nt][0] + b0, acc[nt][1] + b1);
            ((float2*)p1)[0] = make_float2(acc[nt][2] + b0, acc[nt][3] + b1);
        }
    }
}

// ---------------- pipelined round kernel ----------------
// Phase z = blockIdx.z, t = r - z:
//  z=0: h1[t] = tanh(xp0[t] + Whh0 @ h1[t-1])        2-term
//  z=1: xp1[t] = Wih1 @ h1[t] + bih1 + bhh1          1-term (hi only)
//  z=2: h2[t] = tanh(xp1[t] + Whh1 @ h2[t-1])        2-term
__global__ void __launch_bounds__(256) round_kernel(
    int r, const float* __restrict__ bih1, const float* __restrict__ bhh1)
{
    const int z = blockIdx.z;
    const int t = r - z;
    if (t < 0 || t >= TT) return;

    extern __shared__ __align__(16) char smem_raw[];
    uint32_t sm = smem_u32(smem_raw);
    const size_t TH = (size_t)TT * HH;

    const hf *A, *Whi, *Wlo;
    size_t rowA0 = 0;
    bool doGemm = true;
    bool single = false;
    if (z == 0) {
        A = g_h1; Whi = g_Whh0hi; Wlo = g_Whh0lo;
        rowA0 = (size_t)(t - 1) * HH;  doGemm = (t > 0);
    } else if (z == 1) {
        A = g_h1; Whi = g_Wih1hi; Wlo = g_Wih1lo;
        rowA0 = (size_t)t * HH;  single = true;
    } else {
        A = g_h2; Whi = g_Whh1hi; Wlo = g_Whh1lo;
        rowA0 = (size_t)(t - 1) * HH;  doGemm = (t > 0);
    }

    const int tid = threadIdx.x;
    const int bn = blockIdx.x, bm = blockIdx.y;
    const int lane = tid & 31, wid = tid >> 5;
    const int wg = wid >> 2, wq = wid & 3;
    const int wm = wq & 1, wn = wq >> 1;
    const int g = lane >> 2, tg = lane & 3;

    float acc[4][4];
    #pragma unroll
    for (int i = 0; i < 4; i++)
        #pragma unroll
        for (int j = 0; j < 4; j++) acc[i][j] = 0.f;

    if (doGemm)
        run_ml(acc, A, Whi, Wlo, rowA0, TH, HH, sm, tid, bm, bn, wg, wq, single);

    // cross-group reduction
    float* red = (float*)smem_raw;
    if (wg == 1) {
        #pragma unroll
        for (int nt = 0; nt < 4; nt++)
            #pragma unroll
            for (int j = 0; j < 4; j++) red[(tid - 128) * 16 + nt * 4 + j] = acc[nt][j];
    }
    __syncthreads();
    if (wg == 0) {
        #pragma unroll
        for (int nt = 0; nt < 4; nt++)
            #pragma unroll
            for (int j = 0; j < 4; j++) acc[nt][j] += red[tid * 16 + nt * 4 + j];

        const int r0 = bm * 32 + wm * 16 + g;
        const size_t rowT = (size_t)t * HH;
        #pragma unroll
        for (int nt = 0; nt < 4; nt++) {
            int n = bn * 64 + wn * 32 + nt * 8 + tg * 2;
            if (z == 1) {
                float b0 = bih1[n] + bhh1[n], b1 = bih1[n + 1] + bhh1[n + 1];
                float* p0 = g_xp1 + rowT + (size_t)r0 * TH + n;
                float* p1 = g_xp1 + rowT + (size_t)(r0 + 8) * TH + n;
                ((float2*)p0)[0] = make_float2(acc[nt][0] + b0, acc[nt][1] + b1);
                ((float2*)p1)[0] = make_float2(acc[nt][2] + b0, acc[nt][3] + b1);
            } else {
                const float* xps = (z == 0) ? g_xp0 : g_xp1;
                hf* oH = (z == 0) ? g_h1 : g_h2;
                #pragma unroll
                for (int h = 0; h < 2; h++) {
                    int rr = r0 + h * 8;
                    const float2 xp2 = *(const float2*)(xps + rowT + (size_t)rr * TH + n);
                    float v0 = fast_tanh(acc[nt][h * 2 + 0] + xp2.x);
                    float v1 = fast_tanh(acc[nt][h * 2 + 1] + xp2.y);
                    __half2 hp;
                    hp.x = __float2half(v0);
                    hp.y = __float2half(v1);
                    *(__half2*)(oH + rowT + (size_t)rr * TH + n) = hp;
                }
            }
        }
    }
}

// ---------------- host ----------------
extern "C" void kernel_launch(void* const* d_in, const int* in_sizes, int n_in,
                              void* d_out, int out_size)
{
    const float* x    = (const float*)d_in[0];
    const float* Wih0 = (const float*)d_in[1];
    const float* Whh0 = (const float*)d_in[2];
    const float* bih0 = (const float*)d_in[3];
    const float* bhh0 = (const float*)d_in[4];
    const float* Wih1 = (const float*)d_in[5];
    const float* Whh1 = (const float*)d_in[6];
    const float* bih1 = (const float*)d_in[7];
    const float* bhh1 = (const float*)d_in[8];
    const float* fcW  = (const float*)d_in[9];
    const float* fcb  = (const float*)d_in[10];
    float* out = (float*)d_out;

    void *p_xp0, *p_xh, *p_h2, *p_i0h, *p_i0l, *p_r0h, *p_r0l;
    void *p_i1h, *p_i1l, *p_r1h, *p_r1l, *p_fch, *p_fcl;
    cudaGetSymbolAddress(&p_xp0, g_xp0);
    cudaGetSymbolAddress(&p_xh, g_xh);
    cudaGetSymbolAddress(&p_h2, g_h2);
    cudaGetSymbolAddress(&p_i0h, g_Wih0hi); cudaGetSymbolAddress(&p_i0l, g_Wih0lo);
    cudaGetSymbolAddress(&p_r0h, g_Whh0hi); cudaGetSymbolAddress(&p_r0l, g_Whh0lo);
    cudaGetSymbolAddress(&p_i1h, g_Wih1hi); cudaGetSymbolAddress(&p_i1l, g_Wih1lo);
    cudaGetSymbolAddress(&p_r1h, g_Whh1hi); cudaGetSymbolAddress(&p_r1l, g_Whh1lo);
    cudaGetSymbolAddress(&p_fch, g_fcWhi);  cudaGetSymbolAddress(&p_fcl, g_fcWlo);

    static bool attr_done = false;
    if (!attr_done) {
        cudaFuncSetAttribute(gemm_kernel<0>, cudaFuncAttributeMaxDynamicSharedMemorySize, SMEM_DYN);
        cudaFuncSetAttribute(gemm_kernel<2>, cudaFuncAttributeMaxDynamicSharedMemorySize, SMEM_DYN);
        cudaFuncSetAttribute(round_kernel,   cudaFuncAttributeMaxDynamicSharedMemorySize, SMEM_DYN);
        attr_done = true;
    }

    // 1. conversions / splits
    cvt_kernel<<<(BB * TT * II + 255) / 256, 256>>>(x, (hf*)p_xh, BB * TT * II);
    splitw_kernel<<<(HH * II + 255) / 256, 256>>>(Wih0, (hf*)p_i0h, (hf*)p_i0l, HH * II);
    splitw_kernel<<<(HH * HH + 255) / 256, 256>>>(Whh0, (hf*)p_r0h, (hf*)p_r0l, HH * HH);
    splitw_kernel<<<(HH * HH + 255) / 256, 256>>>(Wih1, (hf*)p_i1h, (hf*)p_i1l, HH * HH);
    splitw_kernel<<<(HH * HH + 255) / 256, 256>>>(Whh1, (hf*)p_r1h, (hf*)p_r1l, HH * HH);
    split_pad_fc<<<(HH * HH + 255) / 256, 256>>>(fcW, (hf*)p_fch, (hf*)p_fcl);

    const size_t TH = (size_t)TT * HH;
    const dim3 projGrid(HH / 64, (BB * TT) / 32);   // (16, 1024)
    const dim3 roundGrid(HH / 64, BB / 32, 3);      // (16, 8, 3) = 384 CTAs
    const dim3 fcGrid(HH / 64, BB / 32);            // (16, 8)

    // 2. layer0 bulk input projection: xp0 = x @ Wih0^T + bih0 + bhh0
    gemm_kernel<0><<<projGrid, 256, SMEM_DYN>>>(
        (hf*)p_xh, 0, II, II,
        (hf*)p_i0h, (hf*)p_i0l, bih0, bhh0,
        (float*)p_xp0, 0, HH);

    // 3. pipelined rounds: layer0 step (2-term) | layer1 proj (1-term) | layer1 step (2-term)
    for (int r = 0; r <= TT + 1; r++)
        round_kernel<<<roundGrid, 256, SMEM_DYN>>>(r, bih1, bhh1);

    // 4. FC on h2[:, T-1, :]
    gemm_kernel<2><<<fcGrid, 256, SMEM_DYN>>>(
        (hf*)p_h2, (size_t)(TT - 1) * HH, TH, HH,
        (hf*)p_fch, (hf*)p_fcl, fcb, nullptr,
        out, 0, CC);
}